// round 11
// baseline (speedup 1.0000x reference)
#include <cuda_runtime.h>
#include <cstdint>

#define HH 1024
#define WW 1024
#define XV 4      // output pixels per thread in x (one float4)
#define RWS 32    // output rows per thread strip (halo amp 1.125x)

__device__ __forceinline__ void loadrow(float* wr, const float* __restrict__ ip,
                                        int y, int x0, bool interior_x, float INFv) {
    if (y < 0 || y >= HH) {
#pragma unroll
        for (int c = 0; c < 12; ++c) wr[c] = INFv;
    } else if (interior_x) {
        const float4* p = reinterpret_cast<const float4*>(ip + (size_t)y * WW + (x0 - 4));
        float4 a = p[0], b = p[1], c4 = p[2];
        wr[0] = a.x;  wr[1] = a.y;  wr[2] = a.z;  wr[3] = a.w;
        wr[4] = b.x;  wr[5] = b.y;  wr[6] = b.z;  wr[7] = b.w;
        wr[8] = c4.x; wr[9] = c4.y; wr[10] = c4.z; wr[11] = c4.w;
    } else {
#pragma unroll
        for (int c = 0; c < 12; ++c) {
            int col = x0 - 4 + c;
            wr[c] = (col >= 0 && col < WW) ? ip[(size_t)y * WW + col] : INFv;
        }
    }
}

// One output row: load fresh row into static slot (u+4)%5, R1 serial-chain
// compute from static slots (u+i)%5, float4 store. u = row index mod 5 (static).
template <int U>
__device__ __forceinline__ void do_row(float (&w)[5][12], const float* fv,
                                       const float* __restrict__ ip,
                                       float* __restrict__ op,
                                       int y, int x0, bool interior_x, float INFv) {
    loadrow(w[(U + 4) % 5], ip, y + 2, x0, interior_x, INFv);

    float acc[XV];
    {
        const float f0 = fv[0];
#pragma unroll
        for (int c = 0; c < XV; ++c) acc[c] = w[U % 5][c + 2] - f0;
    }
#pragma unroll
    for (int i = 0; i < 5; ++i) {
        const int s = (U + i) % 5;   // compile-time static ring slot
#pragma unroll
        for (int j = 0; j < 5; ++j) {
            if (i == 0 && j == 0) continue;
            const float f = fv[i * 5 + j];
#pragma unroll
            for (int c = 0; c < XV; ++c)
                acc[c] = fminf(acc[c], w[s][c + j + 2] - f);
        }
    }

    float4 o;
    o.x = acc[0]; o.y = acc[1]; o.z = acc[2]; o.w = acc[3];
    *reinterpret_cast<float4*>(op + (size_t)y * WW + x0) = o;
}

__global__ __launch_bounds__(128)
void erosion5x5_loop5_kernel(const float* __restrict__ img,
                             const float* __restrict__ filt,
                             float* __restrict__ out) {
    const int x0 = (blockIdx.x * blockDim.x + threadIdx.x) * XV;
    const int y0 = blockIdx.y * RWS;
    const size_t plane = (size_t)blockIdx.z * (size_t)HH * (size_t)WW;
    const float* ip = img + plane;
    float* op = out + plane;

    float fv[25];
#pragma unroll
    for (int t = 0; t < 25; ++t) fv[t] = filt[t];

    const float INFv = __int_as_float(0x7f800000);
    const bool interior_x = (x0 >= 4) && (x0 + 8 <= WW);

    // Ring: slot k%5 holds input row y0+k-2. Prologue fills k=0..3.
    float w[5][12];
#pragma unroll
    for (int k = 0; k < 4; ++k)
        loadrow(w[k], ip, y0 + k - 2, x0, interior_x, INFv);

    // 6 rolled groups x 5 unrolled rows: slot indices static (period-5 ring),
    // code footprint ~1/6 of a full unroll -> fits I$ L1.5.
#pragma unroll 1
    for (int rb = 0; rb < 6; ++rb) {
        const int y = y0 + rb * 5;
        do_row<0>(w, fv, ip, op, y + 0, x0, interior_x, INFv);
        do_row<1>(w, fv, ip, op, y + 1, x0, interior_x, INFv);
        do_row<2>(w, fv, ip, op, y + 2, x0, interior_x, INFv);
        do_row<3>(w, fv, ip, op, y + 3, x0, interior_x, INFv);
        do_row<4>(w, fv, ip, op, y + 4, x0, interior_x, INFv);
    }
    // Epilogue rows 30, 31 (ring phase u=0,1)
    do_row<0>(w, fv, ip, op, y0 + 30, x0, interior_x, INFv);
    do_row<1>(w, fv, ip, op, y0 + 31, x0, interior_x, INFv);
}

extern "C" void kernel_launch(void* const* d_in, const int* in_sizes, int n_in,
                              void* d_out, int out_size) {
    const float* image = (const float*)d_in[0];
    const float* filt  = (const float*)d_in[1];
    float* out = (float*)d_out;

    const int planes = in_sizes[0] / (HH * WW);  // 32*3 = 96

    dim3 block(128, 1, 1);
    dim3 grid(WW / (128 * XV), HH / RWS, planes);  // (2, 32, 96)
    erosion5x5_loop5_kernel<<<grid, block>>>(image, filt, out);
}